// round 10
// baseline (speedup 1.0000x reference)
#include <cuda_runtime.h>

// Shapes: B=32, N=128, IN_CH=16, IN_DIM=32, OUT_CH=32, OUT_DIM=32, P=2048
// x[b,n,c,i]  : b*65536 + n*512 + c*32 + i
// W[c,o,i,j]  : c*32768 + o*1024 + i*32 + j
// y/z[b,o,c,i]: (b*32+o)*512 + c*32 + i
// b_ij is linear in the z-history: b_t = x · (z_0+..+z_{t-1}); never materialized.

typedef unsigned long long u64;

__device__ __forceinline__ u64 pk(float a, float b) {
    u64 r; asm("mov.b64 %0,{%1,%2};" : "=l"(r) : "f"(a), "f"(b)); return r;
}
__device__ __forceinline__ void upk(u64 p, float& a, float& b) {
    asm("mov.b64 {%0,%1},%2;" : "=f"(a), "=f"(b) : "l"(p));
}
__device__ __forceinline__ void fma2(u64& d, u64 a, u64 b) {
    asm("fma.rn.f32x2 %0,%1,%2,%0;" : "+l"(d) : "l"(a), "l"(b));
}
__device__ __forceinline__ u64 add2(u64 a, u64 b) {
    u64 r; asm("add.rn.f32x2 %0,%1,%2;" : "=l"(r) : "l"(a), "l"(b)); return r;
}
__device__ __forceinline__ u64 shflx(u64 v, int m) {
    unsigned lo = (unsigned)v, hi = (unsigned)(v >> 32);
    lo = __shfl_xor_sync(0xffffffffu, lo, m);
    hi = __shfl_xor_sync(0xffffffffu, hi, m);
    return ((u64)hi << 32) | lo;
}

__device__ __align__(16) float g_y  [32*32*16*32];
__device__ __align__(16) float g_y0p[32*8*512];
__device__ __align__(16) float g_z  [32*32*16*32];
__device__ float g_sp [32*16*32];
__device__ float g_mp [32*16*32];
__device__ float g_t  [32*32];

// ---------------------------------------------------------------------------
__global__ void k_y0(const float* __restrict__ x)
{
    int b = blockIdx.x >> 3, k = blockIdx.x & 7, t = threadIdx.x;
    const float* xb = x + b*65536 + k*16*512 + t;
    float acc = 0.f;
    #pragma unroll
    for (int n = 0; n < 16; ++n) acc += xb[n*512];
    g_y0p[b*4096 + k*512 + t] = acc * (1.f/2048.f);
}

// ---------------------------------------------------------------------------
// k_f: fused routing step per (b,c) tile. grid 512, 512 threads.
// ---------------------------------------------------------------------------
__global__ __launch_bounds__(512) void k_f(const float* __restrict__ x,
                                           int use_toff, int write_mp)
{
    __shared__ __align__(16) float x_sm[128*32];   // [n][i]
    __shared__ __align__(16) float w_sm[128*36];   // [n][o] padded
    __shared__ __align__(16) float z_sm[32*34];    // [o][i] padded
    __shared__ float mred[16*33];
    __shared__ float sred[16*33];
    __shared__ float toff_sm[32];
    __shared__ u64   yred[512];                    // [oq][2][lane]
    int b = blockIdx.x >> 4, c = blockIdx.x & 15;
    int t = threadIdx.x, lane = t & 31, wid = t >> 5;

    const float* xb = x + b*65536 + c*32;
    #pragma unroll
    for (int nn = 0; nn < 8; ++nn) {
        int n = wid*8 + nn;
        x_sm[n*32 + lane] = xb[n*512 + lane];
    }
    {   // z slice staged once, coalesced
        int o = t >> 4, i2 = t & 15;
        float2 vv = *(const float2*)(g_z + (b*32 + o)*512 + c*32 + 2*i2);
        *(float2*)(z_sm + o*34 + 2*i2) = vv;
    }
    if (t < 32) toff_sm[t] = use_toff ? g_t[b*32 + t] : 0.f;
    __syncthreads();

    u64 zr[16];
    #pragma unroll
    for (int q = 0; q < 16; ++q) zr[q] = *(const u64*)(z_sm + lane*34 + 2*q);

    float toff = toff_sm[lane];
    float bmax = -1e30f, ssum = 0.f;
    #pragma unroll
    for (int nn = 0; nn < 8; ++nn) {
        int n = wid*8 + nn;
        const ulonglong2* xr = (const ulonglong2*)(x_sm + n*32);  // broadcast
        u64 a0 = 0, a1 = 0;
        #pragma unroll
        for (int q = 0; q < 8; ++q) {
            ulonglong2 xv = xr[q];
            fma2(a0, xv.x, zr[2*q]);
            fma2(a1, xv.y, zr[2*q+1]);
        }
        float l0,h0,l1,h1; upk(a0,l0,h0); upk(a1,l1,h1);
        float du = (l0+h0)+(l1+h1);
        bmax = fmaxf(bmax, du);
        float w = __expf(du - toff);
        ssum += w;
        w_sm[n*36 + lane] = w;                          // bank 4n+lane: CF
    }
    mred[wid*33 + lane] = bmax;
    sred[wid*33 + lane] = ssum;
    __syncthreads();
    if (t < 32) {
        float m = -1e30f, s = 0.f;
        #pragma unroll
        for (int g = 0; g < 16; ++g) {
            m = fmaxf(m, mred[g*33 + t]);
            s += sred[g*33 + t];
        }
        if (write_mp) g_mp[b*512 + c*32 + t] = m;
        g_sp[b*512 + c*32 + t] = s;
    }

    // phase2: warp = (oq in [0,8)) x (nh in [0,2)); thread i = lane
    int oq = wid & 7, nh = wid >> 3, o0 = oq*4;
    u64 acc0 = 0, acc1 = 0;
    #pragma unroll 4
    for (int nn = 0; nn < 64; ++nn) {
        int n = nh*64 + nn;
        float xv = x_sm[n*32 + lane];                    // CF, 1 wf
        ulonglong2 wv = *(const ulonglong2*)(w_sm + n*36 + o0); // broadcast
        u64 xs = pk(xv, xv);
        fma2(acc0, wv.x, xs);
        fma2(acc1, wv.y, xs);
    }
    if (nh == 1) {
        yred[(oq*2+0)*32 + lane] = acc0;
        yred[(oq*2+1)*32 + lane] = acc1;
    }
    __syncthreads();
    if (nh == 0) {
        acc0 = add2(acc0, yred[(oq*2+0)*32 + lane]);
        acc1 = add2(acc1, yred[(oq*2+1)*32 + lane]);
        float p0,p1,p2,p3; upk(acc0,p0,p1); upk(acc1,p2,p3);
        float* ybp = g_y + b*16384 + c*32 + lane;
        ybp[(o0  )*512] = p0; ybp[(o0+1)*512] = p1;
        ybp[(o0+2)*512] = p2; ybp[(o0+3)*512] = p3;
    }
}

// ---------------------------------------------------------------------------
// k_s: s[b,o,j] = (1/S) sum_ci y[b,o,ci] W[ci,o,j]; squash -> v,a;
//      z_cum[b,o,ci] (+)= sum_j W[ci,o,j] v[b,o,j]
// grid 256 (o | b-group of 4), 512 threads.
// W in plain [ci][36] smem layout: all accesses conflict-free.
// ---------------------------------------------------------------------------
#define SMEM_S ((18432 + 2048 + 1024 + 128) * 4)
__global__ __launch_bounds__(512) void k_s(const float* __restrict__ Wg,
                                           int mode, float* __restrict__ out)
{
    extern __shared__ __align__(16) float sm[];
    float* W36  = sm;                  // [512][36]
    float* y_sm = sm + 18432;          // [4][512]
    float* part = sm + 20480;          // [8][4][32]
    float* v_sm = sm + 21504;          // [4][32]

    int o  = blockIdx.x & 31;
    int b0 = (blockIdx.x >> 5) * 4;
    int t  = threadIdx.x;

    // W o-slice: thread t owns row ci = t (c = t>>5, i = t&31)
    {
        const float4* src = (const float4*)(Wg + (t>>5)*32768 + o*1024 + (t&31)*32);
        float4* dst = (float4*)(W36 + t*36);     // bank 4t+4k: CF per quarter
        #pragma unroll
        for (int k = 0; k < 8; ++k) dst[k] = src[k];
    }
    {
        int bb = t >> 7, ci4 = t & 127;
        if (mode == 0) {
            const float4* yp = (const float4*)g_y0p + (b0+bb)*1024 + ci4;
            float4 acc = yp[0];
            #pragma unroll
            for (int k = 1; k < 8; ++k) {
                float4 v = yp[k*128];
                acc.x += v.x; acc.y += v.y; acc.z += v.z; acc.w += v.w;
            }
            ((float4*)y_sm)[t] = acc;
        } else {
            ((float4*)y_sm)[t] =
                ((const float4*)(g_y + (b0+bb)*16384 + o*512))[ci4];
        }
    }
    __syncthreads();

    int j = t & 31, w5 = t >> 5;
    int e = w5 & 7, bp = w5 >> 3;       // ci-eighth, b-pair

    // s partials: warp covers 64 ci for 2 b's; scalar W (CF), broadcast y
    float accA = 0.f, accB = 0.f;
    {
        const float* yA = y_sm + (bp*2    )*512 + e*64;
        const float* yB = y_sm + (bp*2 + 1)*512 + e*64;
        const float* wp0 = W36 + (e*64)*36 + j;
        #pragma unroll 4
        for (int q = 0; q < 16; ++q) {
            float4 ya = *(const float4*)(yA + 4*q);
            float4 yb = *(const float4*)(yB + 4*q);
            const float* wp = wp0 + q*144;
            float w0 = wp[0], w1 = wp[36], w2 = wp[72], w3 = wp[108];
            accA = fmaf(ya.w,w3, fmaf(ya.z,w2, fmaf(ya.y,w1, fmaf(ya.x,w0, accA))));
            accB = fmaf(yb.w,w3, fmaf(yb.z,w2, fmaf(yb.y,w1, fmaf(yb.x,w0, accB))));
        }
    }
    part[(e*4 + bp*2    )*32 + j] = accA;
    part[(e*4 + bp*2 + 1)*32 + j] = accB;
    __syncthreads();

    if (w5 < 4) {
        int b = b0 + w5;
        float sacc = 0.f;
        #pragma unroll
        for (int ee = 0; ee < 8; ++ee) sacc += part[(ee*4 + w5)*32 + j];
        float Sinv = 1.f;
        if (mode != 0) {
            float sv = (j < 16) ? g_sp[b*512 + j*32 + o] : 0.f;
            #pragma unroll
            for (int s2 = 16; s2; s2 >>= 1) sv += __shfl_xor_sync(0xffffffffu, sv, s2);
            Sinv = 1.f / sv;
            if (mode == 1) {
                float mv = (j < 16) ? g_mp[b*512 + j*32 + o] : -1e30f;
                #pragma unroll
                for (int s2 = 16; s2; s2 >>= 1)
                    mv = fmaxf(mv, __shfl_xor_sync(0xffffffffu, mv, s2));
                if (j == 0) g_t[b*32 + o] = mv;
            }
        }
        float acc = sacc * Sinv;
        float mag_sq = acc*acc;
        #pragma unroll
        for (int s2 = 16; s2; s2 >>= 1) mag_sq += __shfl_xor_sync(0xffffffffu, mag_sq, s2);
        float mag = sqrtf(mag_sq) + 1e-11f;
        float a   = mag_sq / (1.f + mag_sq);
        float v   = acc * (a / mag);
        v_sm[w5*32 + j] = v;
        if (mode == 2) {
            out[(b*32 + o)*32 + j] = v;
            if (j == 0) out[32768 + b*32 + o] = a;
        }
    }
    if (mode == 2) return;
    __syncthreads();

    // z: lane = (b = lane>>3, jq = lane&7); warp w5 covers ci-pairs [w5*16, +16)
    {
        int lb = (t >> 3) & 3, jq = t & 7;
        float4 vv = *(const float4*)(v_sm + lb*32 + 4*jq);
        u64 v0 = pk(vv.x, vv.y), v1 = pk(vv.z, vv.w);
        int pbase = w5 * 16;
        float2* zrow = (float2*)(g_z + ((b0+lb)*32 + o)*512);
        #pragma unroll 4
        for (int pq = 0; pq < 16; ++pq) {
            int ci0 = (pbase + pq)*2;
            ulonglong2 wa = *(const ulonglong2*)(W36 + ci0*36 + 4*jq);      // bcast
            ulonglong2 wb = *(const ulonglong2*)(W36 + (ci0+1)*36 + 4*jq);  // bcast
            u64 d0 = 0, d1 = 0;
            fma2(d0, wa.x, v0); fma2(d0, wa.y, v1);
            fma2(d1, wb.x, v0); fma2(d1, wb.y, v1);
            float e0,e1,f0,f1; upk(d0,e0,e1); upk(d1,f0,f1);
            u64 zp = pk(e0+e1, f0+f1);      // (z_ci0, z_ci1) partial (4 j's)
            zp = add2(zp, shflx(zp, 4));
            zp = add2(zp, shflx(zp, 2));
            zp = add2(zp, shflx(zp, 1));
            if (jq == 0) {
                float zl, zh; upk(zp, zl, zh);
                float2* dst = zrow + (pbase + pq);
                if (mode == 1) { float2 ov = *dst; zl += ov.x; zh += ov.y; }
                *dst = make_float2(zl, zh);
            }
        }
    }
}

// ---------------------------------------------------------------------------
extern "C" void kernel_launch(void* const* d_in, const int* in_sizes, int n_in,
                              void* d_out, int out_size)
{
    const float* x = (const float*)d_in[0];
    const float* W = (const float*)(n_in > 1 ? d_in[1] : d_in[0]);
    for (int i = 0; i < n_in; ++i) {
        if (in_sizes[i] == 32*128*16*32)      x = (const float*)d_in[i];
        else if (in_sizes[i] == 16*32*32*32)  W = (const float*)d_in[i];
    }
    float* out = (float*)d_out;

    cudaFuncSetAttribute(k_s, cudaFuncAttributeMaxDynamicSharedMemorySize, SMEM_S);

    k_y0<<<256, 512>>>(x);
    k_s <<<256, 512, SMEM_S>>>(W, 0, nullptr);   // v0, z_cum = z0
    k_f <<<512, 512>>>(x, 0, 1);                 // y1, S + max partials
    k_s <<<256, 512, SMEM_S>>>(W, 1, nullptr);   // v1, z_cum += z1, g_t
    k_f <<<512, 512>>>(x, 1, 0);                 // y2, S
    k_s <<<256, 512, SMEM_S>>>(W, 2, out);       // v2, a2 -> out
}

// round 11
// speedup vs baseline: 1.3718x; 1.3718x over previous
#include <cuda_runtime.h>

// Shapes: B=32, N=128, IN_CH=16, IN_DIM=32, OUT_CH=32, OUT_DIM=32, P=2048
// x[b,n,c,i]  : b*65536 + n*512 + c*32 + i
// W[c,o,i,j]  : c*32768 + o*1024 + i*32 + j
// y/z[b,o,c,i]: (b*32+o)*512 + c*32 + i
// b_ij is linear in the z-history: b_t = x · (z_0+..+z_{t-1}); never materialized.

typedef unsigned long long u64;

__device__ __forceinline__ u64 pk(float a, float b) {
    u64 r; asm("mov.b64 %0,{%1,%2};" : "=l"(r) : "f"(a), "f"(b)); return r;
}
__device__ __forceinline__ void upk(u64 p, float& a, float& b) {
    asm("mov.b64 {%0,%1},%2;" : "=f"(a), "=f"(b) : "l"(p));
}
__device__ __forceinline__ void fma2(u64& d, u64 a, u64 b) {
    asm("fma.rn.f32x2 %0,%1,%2,%0;" : "+l"(d) : "l"(a), "l"(b));
}
__device__ __forceinline__ u64 add2(u64 a, u64 b) {
    u64 r; asm("add.rn.f32x2 %0,%1,%2;" : "=l"(r) : "l"(a), "l"(b)); return r;
}

__device__ __align__(16) float g_y  [32*32*16*32];
__device__ __align__(16) float g_y0p[32*8*512];
__device__ __align__(16) float g_z  [32*32*16*32];
__device__ float g_sp [32*16*32];
__device__ float g_mp [32*16*32];
__device__ float g_t  [32*32];

// ---------------------------------------------------------------------------
__global__ void k_y0(const float* __restrict__ x)
{
    int b = blockIdx.x >> 3, k = blockIdx.x & 7, t = threadIdx.x;
    const float* xb = x + b*65536 + k*16*512 + t;
    float acc = 0.f;
    #pragma unroll
    for (int n = 0; n < 16; ++n) acc += xb[n*512];
    g_y0p[b*4096 + k*512 + t] = acc * (1.f/2048.f);
}

// ---------------------------------------------------------------------------
// k_f: fused routing step per (b,c) tile. grid 512, 512 threads. (R10 design)
// ---------------------------------------------------------------------------
__global__ __launch_bounds__(512) void k_f(const float* __restrict__ x,
                                           int use_toff, int write_mp)
{
    __shared__ __align__(16) float x_sm[128*32];
    __shared__ __align__(16) float w_sm[128*36];
    __shared__ __align__(16) float z_sm[32*34];
    __shared__ float mred[16*33];
    __shared__ float sred[16*33];
    __shared__ float toff_sm[32];
    __shared__ u64   yred[512];
    int b = blockIdx.x >> 4, c = blockIdx.x & 15;
    int t = threadIdx.x, lane = t & 31, wid = t >> 5;

    const float* xb = x + b*65536 + c*32;
    #pragma unroll
    for (int nn = 0; nn < 8; ++nn) {
        int n = wid*8 + nn;
        x_sm[n*32 + lane] = xb[n*512 + lane];
    }
    {
        int o = t >> 4, i2 = t & 15;
        float2 vv = *(const float2*)(g_z + (b*32 + o)*512 + c*32 + 2*i2);
        *(float2*)(z_sm + o*34 + 2*i2) = vv;
    }
    if (t < 32) toff_sm[t] = use_toff ? g_t[b*32 + t] : 0.f;
    __syncthreads();

    u64 zr[16];
    #pragma unroll
    for (int q = 0; q < 16; ++q) zr[q] = *(const u64*)(z_sm + lane*34 + 2*q);

    float toff = toff_sm[lane];
    float bmax = -1e30f, ssum = 0.f;
    #pragma unroll
    for (int nn = 0; nn < 8; ++nn) {
        int n = wid*8 + nn;
        const ulonglong2* xr = (const ulonglong2*)(x_sm + n*32);
        u64 a0 = 0, a1 = 0;
        #pragma unroll
        for (int q = 0; q < 8; ++q) {
            ulonglong2 xv = xr[q];
            fma2(a0, xv.x, zr[2*q]);
            fma2(a1, xv.y, zr[2*q+1]);
        }
        float l0,h0,l1,h1; upk(a0,l0,h0); upk(a1,l1,h1);
        float du = (l0+h0)+(l1+h1);
        bmax = fmaxf(bmax, du);
        float w = __expf(du - toff);
        ssum += w;
        w_sm[n*36 + lane] = w;
    }
    mred[wid*33 + lane] = bmax;
    sred[wid*33 + lane] = ssum;
    __syncthreads();
    if (t < 32) {
        float m = -1e30f, s = 0.f;
        #pragma unroll
        for (int g = 0; g < 16; ++g) {
            m = fmaxf(m, mred[g*33 + t]);
            s += sred[g*33 + t];
        }
        if (write_mp) g_mp[b*512 + c*32 + t] = m;
        g_sp[b*512 + c*32 + t] = s;
    }

    int oq = wid & 7, nh = wid >> 3, o0 = oq*4;
    u64 acc0 = 0, acc1 = 0;
    #pragma unroll 4
    for (int nn = 0; nn < 64; ++nn) {
        int n = nh*64 + nn;
        float xv = x_sm[n*32 + lane];
        ulonglong2 wv = *(const ulonglong2*)(w_sm + n*36 + o0);
        u64 xs = pk(xv, xv);
        fma2(acc0, wv.x, xs);
        fma2(acc1, wv.y, xs);
    }
    if (nh == 1) {
        yred[(oq*2+0)*32 + lane] = acc0;
        yred[(oq*2+1)*32 + lane] = acc1;
    }
    __syncthreads();
    if (nh == 0) {
        acc0 = add2(acc0, yred[(oq*2+0)*32 + lane]);
        acc1 = add2(acc1, yred[(oq*2+1)*32 + lane]);
        float p0,p1,p2,p3; upk(acc0,p0,p1); upk(acc1,p2,p3);
        float* ybp = g_y + b*16384 + c*32 + lane;
        ybp[(o0  )*512] = p0; ybp[(o0+1)*512] = p1;
        ybp[(o0+2)*512] = p2; ybp[(o0+3)*512] = p3;
    }
}

// ---------------------------------------------------------------------------
// k_s: grid 128 (o | b-group of 8), 512 threads. W read into smem ONCE
// (coalesced) and consumed exactly once by s-loop (reuse over 8 b via FFMA2
// on packed b-pairs) and once by z-loop (broadcast rows, lane = b x ci-quad).
// ---------------------------------------------------------------------------
// smem word offsets
#define OFF_W    0        // [512][36] floats
#define OFF_Y2   18432    // [4][512] u64 (as words: 8192)
#define OFF_PART 26624    // [16][264] floats
#define OFF_V    30848    // [8][36] floats
#define SMEM_S   ((30848 + 288) * 4)

__global__ __launch_bounds__(512) void k_s(const float* __restrict__ Wg,
                                           int mode, float* __restrict__ out)
{
    extern __shared__ __align__(16) float sm[];
    float* W36  = sm + OFF_W;
    u64*   y2   = (u64*)(sm + OFF_Y2);   // y2[bp*512+ci] = (y[2bp][ci], y[2bp+1][ci])
    float* part = sm + OFF_PART;
    float* v_sm = sm + OFF_V;

    int o  = blockIdx.x & 31;
    int b0 = (blockIdx.x >> 5) * 8;
    int t  = threadIdx.x;

    // W o-slice, coalesced LDG (R7 pattern) -> plain [ci][36]
    const float4* W4 = (const float4*)Wg;
    #pragma unroll
    for (int k = 0; k < 8; ++k) {
        int gi = k*512 + t;
        int c = gi >> 8, tt = gi & 255;
        float4 w = W4[c*8192 + o*256 + tt];
        int i = tt >> 3, j0 = (tt & 7) * 4;
        *(float4*)(W36 + (c*32 + i)*36 + j0) = w;
    }
    // y2: packed b-pairs; thread (bp = t>>7, ci4 = t&127)
    {
        int bp = t >> 7, ci4 = t & 127;
        float4 A, Bv;
        if (mode == 0) {
            const float4* pa = (const float4*)g_y0p + (b0 + 2*bp    )*1024 + ci4;
            const float4* pb = (const float4*)g_y0p + (b0 + 2*bp + 1)*1024 + ci4;
            A = pa[0]; Bv = pb[0];
            #pragma unroll
            for (int k = 1; k < 8; ++k) {
                float4 u = pa[k*128], v = pb[k*128];
                A.x+=u.x; A.y+=u.y; A.z+=u.z; A.w+=u.w;
                Bv.x+=v.x; Bv.y+=v.y; Bv.z+=v.z; Bv.w+=v.w;
            }
        } else {
            A  = ((const float4*)(g_y + (b0+2*bp  )*16384 + o*512))[ci4];
            Bv = ((const float4*)(g_y + (b0+2*bp+1)*16384 + o*512))[ci4];
        }
        u64* dst = y2 + bp*512 + ci4*4;
        dst[0] = pk(A.x, Bv.x); dst[1] = pk(A.y, Bv.y);
        dst[2] = pk(A.z, Bv.z); dst[3] = pk(A.w, Bv.w);
    }
    __syncthreads();

    int j = t & 31, w5 = t >> 5;
    int ci_base = w5 * 32;

    // s-loop: warp owns 32-ci strip, all 8 b; W read once, 4 FFMA2 per ci.
    u64 acc2[4] = {0,0,0,0};
    #pragma unroll 2
    for (int g = 0; g < 8; ++g) {
        int ci0 = ci_base + g*4;
        const float* wp = W36 + ci0*36 + j;
        float w0 = wp[0], w1 = wp[36], w2 = wp[72], w3 = wp[108];  // CF scalar
        u64 p0 = pk(w0,w0), p1 = pk(w1,w1), p2 = pk(w2,w2), p3 = pk(w3,w3);
        #pragma unroll
        for (int bp = 0; bp < 4; ++bp) {
            const ulonglong2* yy = (const ulonglong2*)(y2 + bp*512 + ci0); // bcast
            ulonglong2 ya = yy[0], yb = yy[1];
            fma2(acc2[bp], ya.x, p0);
            fma2(acc2[bp], ya.y, p1);
            fma2(acc2[bp], yb.x, p2);
            fma2(acc2[bp], yb.y, p3);
        }
    }
    #pragma unroll
    for (int bp = 0; bp < 4; ++bp) {
        float sa, sb; upk(acc2[bp], sa, sb);
        part[w5*264 + (2*bp  )*33 + j] = sa;
        part[w5*264 + (2*bp+1)*33 + j] = sb;
    }
    __syncthreads();

    if (w5 < 8) {              // warp = b
        int b = b0 + w5;
        float sacc = 0.f;
        #pragma unroll
        for (int e = 0; e < 16; ++e) sacc += part[e*264 + w5*33 + j];
        float Sinv = 1.f;
        if (mode != 0) {
            float sv = (j < 16) ? g_sp[b*512 + j*32 + o] : 0.f;
            #pragma unroll
            for (int s2 = 16; s2; s2 >>= 1) sv += __shfl_xor_sync(0xffffffffu, sv, s2);
            Sinv = 1.f / sv;
            if (mode == 1) {
                float mv = (j < 16) ? g_mp[b*512 + j*32 + o] : -1e30f;
                #pragma unroll
                for (int s2 = 16; s2; s2 >>= 1)
                    mv = fmaxf(mv, __shfl_xor_sync(0xffffffffu, mv, s2));
                if (j == 0) g_t[b*32 + o] = mv;
            }
        }
        float acc = sacc * Sinv;
        float mag_sq = acc*acc;
        #pragma unroll
        for (int s2 = 16; s2; s2 >>= 1) mag_sq += __shfl_xor_sync(0xffffffffu, mag_sq, s2);
        float mag = sqrtf(mag_sq) + 1e-11f;
        float a   = mag_sq / (1.f + mag_sq);
        float v   = acc * (a / mag);
        v_sm[w5*36 + j] = v;
        if (mode == 2) {
            out[(b*32 + o)*32 + j] = v;
            if (j == 0) out[32768 + b*32 + o] = a;
        }
    }
    if (mode == 2) return;
    __syncthreads();

    // z-loop: lane = (lb = lane&7 -> b, lc = lane>>3 -> ci offset).
    // Warp w5 covers ci strip [w5*32, +32); W rows are 8-lane broadcasts (CF).
    {
        int lb = j & 7, lc = j >> 3;
        u64 vp[16];
        const ulonglong2* vv = (const ulonglong2*)(v_sm + lb*36);  // bcast per lb
        #pragma unroll
        for (int q = 0; q < 8; ++q) { ulonglong2 u = vv[q]; vp[2*q] = u.x; vp[2*q+1] = u.y; }
        float* zrow = g_z + ((b0 + lb)*32 + o)*512;
        #pragma unroll
        for (int it = 0; it < 8; ++it) {
            int ci = ci_base + it*4 + lc;
            const ulonglong2* wr = (const ulonglong2*)(W36 + ci*36);  // bcast x8
            u64 d = 0;
            #pragma unroll
            for (int q = 0; q < 8; ++q) {
                ulonglong2 wq = wr[q];
                fma2(d, wq.x, vp[2*q]);
                fma2(d, wq.y, vp[2*q+1]);
            }
            float zl, zh; upk(d, zl, zh);
            float z = zl + zh;
            if (mode == 1) z += zrow[ci];
            zrow[ci] = z;
        }
    }
}

// ---------------------------------------------------------------------------
extern "C" void kernel_launch(void* const* d_in, const int* in_sizes, int n_in,
                              void* d_out, int out_size)
{
    const float* x = (const float*)d_in[0];
    const float* W = (const float*)(n_in > 1 ? d_in[1] : d_in[0]);
    for (int i = 0; i < n_in; ++i) {
        if (in_sizes[i] == 32*128*16*32)      x = (const float*)d_in[i];
        else if (in_sizes[i] == 16*32*32*32)  W = (const float*)d_in[i];
    }
    float* out = (float*)d_out;

    cudaFuncSetAttribute(k_s, cudaFuncAttributeMaxDynamicSharedMemorySize, SMEM_S);

    k_y0<<<256, 512>>>(x);
    k_s <<<128, 512, SMEM_S>>>(W, 0, nullptr);   // v0, z_cum = z0
    k_f <<<512, 512>>>(x, 0, 1);                 // y1, S + max partials
    k_s <<<128, 512, SMEM_S>>>(W, 1, nullptr);   // v1, z_cum += z1, g_t
    k_f <<<512, 512>>>(x, 1, 0);                 // y2, S
    k_s <<<128, 512, SMEM_S>>>(W, 2, out);       // v2, a2 -> out
}